// round 14
// baseline (speedup 1.0000x reference)
#include <cuda_runtime.h>
#include <cuda_bf16.h>
#include <cstdint>

// ---------------------------------------------------------------------------
// IterativeEmbeddingModel: 2 iterations of
//   emb <- concat(emb@T1, seg_sum(emb[col],row)@T2, seg_sum_anti(...)@T3)
// R14 (on R13 champion, 184.3us):
//  - GEMM phase restructure: phase A = theta0+theta1 k-outer with A fragments
//    hoisted (ldmatrix'd ONCE per ks, reused for both thetas' 24 MMAs);
//    phase B = theta2 (B refilled into buffer0 after phase A, ~1us exposed).
//    LDSM per warp-tile 216 -> 192 (-11% shared traffic), syncs 4 -> 3,
//    both initial B fills hidden under A-convert.
//  - agg / CSR / launch order identical to R13.
//  Split-bf16 3-term math (rel_err ~6e-6, tolerance 1e-3).
// ---------------------------------------------------------------------------

#define NMAX 50000
#define EMAX 400000
#define DIM  192
#define PP   64

// Scratch (device globals; no allocation APIs allowed)
__device__ int      g_count[2 * NMAX];
__device__ int      g_cursor[2 * NMAX];
__device__ int      g_rowstart[2 * (NMAX + 1)];
__device__ int      g_blocksum[2 * 128];
__device__ int      g_cols[2 * EMAX];
__device__ float    g_emb1[(size_t)NMAX * DIM];   // iteration-1 output
__device__ float    g_Y[(size_t)NMAX * 128];      // [Y2 | Y3] per row
__device__ uint32_t g_Bh32[3 * 64 * 96];          // thetas bf16-hi, [t][n][k2]
__device__ uint32_t g_Bl32[3 * 64 * 96];          // thetas bf16-lo

__device__ __forceinline__ uint32_t smem_to_u32(const void* p) {
    uint32_t a;
    asm("{ .reg .u64 t; cvta.to.shared.u64 t, %1; cvt.u32.u64 %0, t; }"
        : "=r"(a) : "l"(p));
    return a;
}

// ---- prep: zero counts + convert thetas to bf16 hi/lo (one kernel) --------
__global__ void prep_kernel(const float* __restrict__ t1,
                            const float* __restrict__ t2,
                            const float* __restrict__ t3) {
    int i = blockIdx.x * blockDim.x + threadIdx.x;
    if (i < 2 * NMAX) g_count[i] = 0;
    if (i < 3 * 64 * 96) {
        int tt = i / 6144;
        int rem = i % 6144;
        int nn = rem / 96;
        int k2 = rem % 96;
        const float* T = (tt == 0) ? t1 : (tt == 1) ? t2 : t3;
        float x0 = T[(size_t)(2 * k2) * 64 + nn];
        float x1 = T[(size_t)(2 * k2 + 1) * 64 + nn];
        __nv_bfloat162 hh = __floats2bfloat162_rn(x0, x1);
        float r0 = x0 - __low2float(hh);
        float r1 = x1 - __high2float(hh);
        __nv_bfloat162 ll = __floats2bfloat162_rn(r0, r1);
        g_Bh32[i] = *(uint32_t*)&hh;
        g_Bl32[i] = *(uint32_t*)&ll;
    }
}

// ---- CSR build ------------------------------------------------------------
__global__ void hist_kernel(const int* __restrict__ e0, const int* __restrict__ e1, int nE) {
    int i = blockIdx.x * blockDim.x + threadIdx.x;
    if (i >= 2 * nE) return;
    int l = (i < nE) ? 0 : 1;
    const int* p = l ? e1 : e0;
    int e = l ? (i - nE) : i;
    int d = p[e];
    atomicAdd(&g_count[l * NMAX + d], 1);
}

__global__ void scan_partial_kernel(int n) {
    __shared__ int warp_sums[16];
    int l = blockIdx.y;
    int i = blockIdx.x * 512 + threadIdx.x;
    int lane = threadIdx.x & 31;
    int w = threadIdx.x >> 5;
    int v = (i < n) ? g_count[l * NMAX + i] : 0;
    int s = v;
#pragma unroll
    for (int o = 1; o < 32; o <<= 1) {
        int t = __shfl_up_sync(0xFFFFFFFFu, s, o);
        if (lane >= o) s += t;
    }
    if (lane == 31) warp_sums[w] = s;
    __syncthreads();
    if (w == 0) {
        int ws = (lane < 16) ? warp_sums[lane] : 0;
#pragma unroll
        for (int o = 1; o < 16; o <<= 1) {
            int t = __shfl_up_sync(0xFFFFFFFFu, ws, o);
            if (lane >= o) ws += t;
        }
        if (lane < 16) warp_sums[lane] = ws;
    }
    __syncthreads();
    int base = (w > 0) ? warp_sums[w - 1] : 0;
    if (i < n) g_rowstart[l * (NMAX + 1) + i] = base + s - v;
    if (threadIdx.x == 511) g_blocksum[l * 128 + blockIdx.x] = base + s;
}

__global__ void add_offsets_kernel(int n, int nb) {
    int l = blockIdx.y;
    int i = blockIdx.x * blockDim.x + threadIdx.x;
    __shared__ int sP;
    if (threadIdx.x < 32) {
        int myblk = blockIdx.x >> 1;
        int s = 0;
        for (int b = threadIdx.x; b < myblk; b += 32) s += g_blocksum[l * 128 + b];
#pragma unroll
        for (int o = 16; o; o >>= 1) s += __shfl_xor_sync(0xFFFFFFFFu, s, o);
        if (threadIdx.x == 0) sP = s;
    }
    if (blockIdx.x == 0 && threadIdx.x >= 32 && threadIdx.x < 64) {
        int lane = threadIdx.x - 32;
        int s = 0;
        for (int b = lane; b < nb; b += 32) s += g_blocksum[l * 128 + b];
#pragma unroll
        for (int o = 16; o; o >>= 1) s += __shfl_xor_sync(0xFFFFFFFFu, s, o);
        if (lane == 0) g_rowstart[l * (NMAX + 1) + n] = s;
    }
    __syncthreads();
    if (i < n) {
        g_rowstart[l * (NMAX + 1) + i] += sP;
        g_cursor[l * NMAX + i] = 0;
    }
}

__global__ void fill_kernel(const int* __restrict__ e0, const int* __restrict__ e1, int nE) {
    int i = blockIdx.x * blockDim.x + threadIdx.x;
    if (i >= 2 * nE) return;
    int l = (i < nE) ? 0 : 1;
    const int* p = l ? e1 : e0;
    int e = l ? (i - nE) : i;
    int d = p[e];
    int c = p[nE + e];
    int pos = g_rowstart[l * (NMAX + 1) + d] + atomicAdd(&g_cursor[l * NMAX + d], 1);
    g_cols[l * EMAX + pos] = c;
}

// ---- mma.sync GEMM (R13 + 2-theta k-outer A-hoist) ------------------------
// Per CTA: rows [rowBase, rowBase+128), all 192 output cols (3 thetas).
// 512 threads / 16 warps: warp (w&7) -> m16 row group, (w>>3) -> n half (32).
// smem: Ah[128][200] | Al[128][200] | Bbuf0{h,l} | Bbuf1{h,l}  (bf16, str 200)
#define A_STRIDE 200
#define OFF_AH 0
#define OFF_AL 51200
#define OFF_B0 102400
#define OFF_B1 153600
#define B_HL   25600      // lo half offset within a B buffer
#define GEMM_SMEM_BYTES 204800

#define MMA(C, A0, A1, A2, A3, B0, B1)                                  \
    asm("mma.sync.aligned.m16n8k16.row.col.f32.bf16.bf16.f32 "          \
        "{%0,%1,%2,%3}, {%4,%5,%6,%7}, {%8,%9}, {%0,%1,%2,%3};"         \
        : "+f"(C.x), "+f"(C.y), "+f"(C.z), "+f"(C.w)                    \
        : "r"(A0), "r"(A1), "r"(A2), "r"(A3), "r"(B0), "r"(B1))

#define LDMX4(R0, R1, R2, R3, ADDR)                                     \
    asm volatile("ldmatrix.sync.aligned.m8n8.x4.shared.b16 "            \
                 "{%0,%1,%2,%3}, [%4];"                                 \
                 : "=r"(R0), "=r"(R1), "=r"(R2), "=r"(R3) : "r"(ADDR))

// Fill one B buffer (theta TT) with cp.async: 64 rows x 24 16B-chunks, hi+lo.
#define CP_FILL(TT, DSTBASE) do {                                             \
    const char* srcH = (const char*)(g_Bh32 + (TT) * 6144);                   \
    const char* srcL = (const char*)(g_Bl32 + (TT) * 6144);                   \
    uint32_t dstH = (DSTBASE);                                                \
    uint32_t dstL = dstH + B_HL;                                              \
    for (int f = tid; f < 1536; f += 512) {                                   \
        int r = f / 24, ck = f % 24;                                          \
        uint32_t doff = (uint32_t)(r * 400 + ck * 16);                        \
        size_t soff = (size_t)r * 384 + (size_t)ck * 16;                      \
        asm volatile("cp.async.cg.shared.global [%0], [%1], 16;"              \
            :: "r"(dstH + doff), "l"(srcH + soff));                           \
        asm volatile("cp.async.cg.shared.global [%0], [%1], 16;"              \
            :: "r"(dstL + doff), "l"(srcL + soff));                           \
    }                                                                         \
    asm volatile("cp.async.commit_group;" ::: "memory");                      \
} while (0)

// 12 MMAs of one theta for this ks (B frags loaded here, A frags reused).
#define THETA_MMAS(C0, C1, C2, C3, B0H, B1H)                                  \
    {                                                                         \
        uint32_t b0h0, b0h1, b1h0, b1h1;                                      \
        LDMX4(b0h0, b0h1, b1h0, b1h1, (B0H) + ko);                            \
        uint32_t b2h0, b2h1, b3h0, b3h1;                                      \
        LDMX4(b2h0, b2h1, b3h0, b3h1, (B1H) + ko);                            \
        uint32_t b0l0, b0l1, b1l0, b1l1;                                      \
        LDMX4(b0l0, b0l1, b1l0, b1l1, (B0H) + B_HL + ko);                     \
        uint32_t b2l0, b2l1, b3l0, b3l1;                                      \
        LDMX4(b2l0, b2l1, b3l0, b3l1, (B1H) + B_HL + ko);                     \
        MMA(C0, ah0, ah1, ah2, ah3, b0h0, b0h1);                              \
        MMA(C1, ah0, ah1, ah2, ah3, b1h0, b1h1);                              \
        MMA(C2, ah0, ah1, ah2, ah3, b2h0, b2h1);                              \
        MMA(C3, ah0, ah1, ah2, ah3, b3h0, b3h1);                              \
        MMA(C0, ah0, ah1, ah2, ah3, b0l0, b0l1);                              \
        MMA(C1, ah0, ah1, ah2, ah3, b1l0, b1l1);                              \
        MMA(C2, ah0, ah1, ah2, ah3, b2l0, b2l1);                              \
        MMA(C3, ah0, ah1, ah2, ah3, b3l0, b3l1);                              \
        MMA(C0, al0, al1, al2, al3, b0h0, b0h1);                              \
        MMA(C1, al0, al1, al2, al3, b1h0, b1h1);                              \
        MMA(C2, al0, al1, al2, al3, b2h0, b2h1);                              \
        MMA(C3, al0, al1, al2, al3, b3h0, b3h1);                              \
    }

__global__ __launch_bounds__(512, 1)
void gemm_kernel(const float* __restrict__ A,
                 float* __restrict__ dst,   // n x 192 (theta0 -> cols 0:64)
                 float* __restrict__ Y,     // n x 128 (theta1|theta2)
                 int n)
{
    extern __shared__ char smem[];
    uint32_t* Ah32 = (uint32_t*)(smem + OFF_AH);
    uint32_t* Al32 = (uint32_t*)(smem + OFF_AL);

    const int tid = threadIdx.x;
    const int w = tid >> 5;
    const int lane = tid & 31;
    const int mw = w & 7;          // m16 row-group index
    const int nh = w >> 3;         // n half (0: cols 0-31, 1: cols 32-63)
    const int q = lane & 3;
    const int rowBase = blockIdx.x * 128;
    const uint32_t sb = smem_to_u32(smem);

    // ---- Prefetch theta0 AND theta1 B (both overlap A conversion) ----
    CP_FILL(0, sb + OFF_B0);
    CP_FILL(1, sb + OFF_B1);

    // ---- Convert A rows to bf16 hi/lo in smem (coalesced, conflict-free) --
    for (int f = tid; f < 128 * 96; f += 512) {
        int r = f / 96, k2 = f % 96;
        int gr = rowBase + r;
        float2 v = make_float2(0.f, 0.f);
        if (gr < n) v = *(const float2*)(A + (size_t)gr * DIM + 2 * k2);
        __nv_bfloat162 hh = __floats2bfloat162_rn(v.x, v.y);
        float r0 = v.x - __low2float(hh);
        float r1 = v.y - __high2float(hh);
        __nv_bfloat162 ll = __floats2bfloat162_rn(r0, r1);
        Ah32[r * 100 + k2] = *(uint32_t*)&hh;
        Al32[r * 100 + k2] = *(uint32_t*)&ll;
    }

    // ---- per-lane ldmatrix base addresses ----
    const int raA = (lane & 7) + ((lane >> 3) & 1) * 8;
    const int kaA = ((lane >> 4) & 1) * 8;
    uint32_t aAh = sb + OFF_AH + (uint32_t)((mw * 16 + raA) * A_STRIDE + kaA) * 2;
    uint32_t aAl = aAh + (OFF_AL - OFF_AH);
    const int rbB = (lane & 7) + ((lane >> 4) & 1) * 8;
    const int kbB = ((lane >> 3) & 1) * 8;
    const uint32_t bOffH = (uint32_t)((nh * 32 + rbB) * A_STRIDE + kbB) * 2;
    const uint32_t bStep = 16 * A_STRIDE * 2;       // tile-pair 1 offset

    const int row0 = rowBase + mw * 16 + (lane >> 2);
    const int row1 = row0 + 8;

    asm volatile("cp.async.wait_group 0;" ::: "memory");
    __syncthreads();   // A + theta0 + theta1 B visible

    // ================= Phase A: theta0 + theta1, k-outer =================
    const uint32_t t0B0 = sb + OFF_B0 + bOffH;
    const uint32_t t0B1 = t0B0 + bStep;
    const uint32_t t1B0 = sb + OFF_B1 + bOffH;
    const uint32_t t1B1 = t1B0 + bStep;

    float4 p0 = make_float4(0.f, 0.f, 0.f, 0.f), p1 = p0, p2 = p0, p3 = p0;
    float4 q0 = p0, q1 = p0, q2 = p0, q3 = p0;

#pragma unroll 2
    for (int ks = 0; ks < 12; ++ks) {
        const uint32_t ko = (uint32_t)ks * 32;       // 16 bf16 = 32 bytes
        uint32_t ah0, ah1, ah2, ah3, al0, al1, al2, al3;
        LDMX4(ah0, ah1, ah2, ah3, aAh + ko);         // A loaded ONCE per ks,
        LDMX4(al0, al1, al2, al3, aAl + ko);         // reused by both thetas
        THETA_MMAS(p0, p1, p2, p3, t0B0, t0B1)       // theta0
        THETA_MMAS(q0, q1, q2, q3, t1B0, t1B1)       // theta1
    }

    // ---- Phase A epilogue: theta0 -> dst, theta1 -> Y ----
#define ST_TILE(C, J, OUTP, OSTR, CB)                                         \
    {                                                                         \
        int col = (CB) + (J) * 8 + 2 * q;                                     \
        if (row0 < n)                                                         \
            *(float2*)((OUTP) + (size_t)row0 * (OSTR) + col) =                \
                make_float2(C.x, C.y);                                        \
        if (row1 < n)                                                         \
            *(float2*)((OUTP) + (size_t)row1 * (OSTR) + col) =                \
                make_float2(C.z, C.w);                                        \
    }
    ST_TILE(p0, 0, dst, DIM, nh * 32) ST_TILE(p1, 1, dst, DIM, nh * 32)
    ST_TILE(p2, 2, dst, DIM, nh * 32) ST_TILE(p3, 3, dst, DIM, nh * 32)
    ST_TILE(q0, 0, Y, 128, nh * 32)   ST_TILE(q1, 1, Y, 128, nh * 32)
    ST_TILE(q2, 2, Y, 128, nh * 32)   ST_TILE(q3, 3, Y, 128, nh * 32)

    // ================= Phase B: theta2 (refill buffer 0) =================
    __syncthreads();                                  // all B0 reads done
    CP_FILL(2, sb + OFF_B0);
    asm volatile("cp.async.wait_group 0;" ::: "memory");
    __syncthreads();                                  // theta2 visible
    {
        float4 c0 = make_float4(0.f, 0.f, 0.f, 0.f), c1 = c0, c2 = c0, c3 = c0;
#pragma unroll 2
        for (int ks = 0; ks < 12; ++ks) {
            const uint32_t ko = (uint32_t)ks * 32;
            uint32_t ah0, ah1, ah2, ah3, al0, al1, al2, al3;
            LDMX4(ah0, ah1, ah2, ah3, aAh + ko);
            LDMX4(al0, al1, al2, al3, aAl + ko);
            THETA_MMAS(c0, c1, c2, c3, t0B0, t0B1)    // buffer0 now holds theta2
        }
        ST_TILE(c0, 0, Y, 128, 64 + nh * 32) ST_TILE(c1, 1, Y, 128, 64 + nh * 32)
        ST_TILE(c2, 2, Y, 128, 64 + nh * 32) ST_TILE(c3, 3, Y, 128, 64 + nh * 32)
    }
#undef ST_TILE
}

// ---- Aggregation: warp per (node, list), atomic-free CSR gather -----------
__global__ void agg_kernel(const float* __restrict__ Y, float* __restrict__ dst, int n)
{
    int gw = (blockIdx.x * blockDim.x + threadIdx.x) >> 5;
    int lane = threadIdx.x & 31;
    int l = blockIdx.y;
    if (gw >= n) return;
    const int* rs = g_rowstart + l * (NMAX + 1);
    const int* cs = g_cols + l * EMAX;
    int s = __ldg(rs + gw);
    int e = __ldg(rs + gw + 1);
    const float* Yb = Y + l * 64 + lane * 2;
    float ax = 0.f, ay = 0.f;
    int j = s;
    for (; j + 4 <= e; j += 4) {
        int c0 = cs[j], c1 = cs[j + 1], c2 = cs[j + 2], c3 = cs[j + 3];
        float2 v0 = *(const float2*)(Yb + (size_t)c0 * 128);
        float2 v1 = *(const float2*)(Yb + (size_t)c1 * 128);
        float2 v2 = *(const float2*)(Yb + (size_t)c2 * 128);
        float2 v3 = *(const float2*)(Yb + (size_t)c3 * 128);
        ax += (v0.x + v1.x) + (v2.x + v3.x);
        ay += (v0.y + v1.y) + (v2.y + v3.y);
    }
    for (; j < e; ++j) {
        float2 v = *(const float2*)(Yb + (size_t)cs[j] * 128);
        ax += v.x; ay += v.y;
    }
    *(float2*)(dst + (size_t)gw * DIM + 64 + l * 64 + lane * 2) =
        make_float2(ax, ay);
}

// ---------------------------------------------------------------------------
extern "C" void kernel_launch(void* const* d_in, const int* in_sizes, int n_in,
                              void* d_out, int out_size)
{
    const float* emb = (const float*)d_in[0];
    const float* t1  = (const float*)d_in[1];
    const float* t2  = (const float*)d_in[2];
    const float* t3  = (const float*)d_in[3];
    const int*   e0  = (const int*)d_in[4];
    const int*   e1  = (const int*)d_in[5];

    int n  = in_sizes[0] / DIM;
    int nE = in_sizes[4] / 2;
    float* out = (float*)d_out;

    void *p_emb1_v, *p_Y_v;
    cudaGetSymbolAddress(&p_emb1_v, g_emb1);
    cudaGetSymbolAddress(&p_Y_v, g_Y);
    float* p_emb1 = (float*)p_emb1_v;
    float* p_Y    = (float*)p_Y_v;

    cudaFuncSetAttribute(gemm_kernel, cudaFuncAttributeMaxDynamicSharedMemorySize,
                         GEMM_SMEM_BYTES);

    int nb = (n + 511) / 512;
    int gemm_blocks = (n + 127) / 128;
    dim3 agg_grid((n * 32 + 255) / 256, 2);

    // gemm1 at launch slot #4 (the slot ncu captures) for profiling.
    prep_kernel<<<(2 * NMAX + 255) / 256, 256>>>(t1, t2, t3);              // 1
    hist_kernel<<<(2 * nE + 255) / 256, 256>>>(e0, e1, nE);                // 2
    dim3 gscan(nb, 2);
    scan_partial_kernel<<<gscan, 512>>>(n);                                // 3
    gemm_kernel<<<gemm_blocks, 512, GEMM_SMEM_BYTES>>>(emb, p_emb1, p_Y, n); // 4
    dim3 goff((n + 255) / 256, 2);
    add_offsets_kernel<<<goff, 256>>>(n, nb);                              // 5
    fill_kernel<<<(2 * nE + 255) / 256, 256>>>(e0, e1, nE);                // 6
    agg_kernel<<<agg_grid, 256>>>(p_Y, p_emb1, n);                         // 7
    gemm_kernel<<<gemm_blocks, 512, GEMM_SMEM_BYTES>>>(p_emb1, out, p_Y, n); // 8
    agg_kernel<<<agg_grid, 256>>>(p_Y, out, n);                            // 9
}

// round 15
// speedup vs baseline: 1.0002x; 1.0002x over previous
#include <cuda_runtime.h>
#include <cuda_bf16.h>
#include <cuda_fp16.h>
#include <cstdint>

// ---------------------------------------------------------------------------
// IterativeEmbeddingModel: 2 iterations of
//   emb <- concat(emb@T1, seg_sum(emb[col],row)@T2, seg_sum_anti(...)@T3)
// R15 (on R13 champion, 184.3us; GEMM plateau established R8-R14):
//  - Y (theta1/theta2 projections, consumed ONLY by aggregation) stored fp16:
//    agg gather bytes halve (256B -> 128B per edge per list). Aggregation is
//    L2-byte-bound, so this is a direct ~40% cut of its runtime.
//    Precision: fp16 ~5e-4/elem, cancels over ~8-edge sums -> ~1e-4 final
//    (tolerance 1e-3; current headroom 6.4e-6).
//  - GEMM body = exact R13 (R14 restructure was neutral, reverted).
// ---------------------------------------------------------------------------

#define NMAX 50000
#define EMAX 400000
#define DIM  192
#define PP   64

// Scratch (device globals; no allocation APIs allowed)
__device__ int      g_count[2 * NMAX];
__device__ int      g_cursor[2 * NMAX];
__device__ int      g_rowstart[2 * (NMAX + 1)];
__device__ int      g_blocksum[2 * 128];
__device__ int      g_cols[2 * EMAX];
__device__ float    g_emb1[(size_t)NMAX * DIM];   // iteration-1 output
__device__ __half   g_Yh[(size_t)NMAX * 128];     // [Y2 | Y3] per row, fp16
__device__ uint32_t g_Bh32[3 * 64 * 96];          // thetas bf16-hi, [t][n][k2]
__device__ uint32_t g_Bl32[3 * 64 * 96];          // thetas bf16-lo

__device__ __forceinline__ uint32_t smem_to_u32(const void* p) {
    uint32_t a;
    asm("{ .reg .u64 t; cvta.to.shared.u64 t, %1; cvt.u32.u64 %0, t; }"
        : "=r"(a) : "l"(p));
    return a;
}

// ---- prep: zero counts + convert thetas to bf16 hi/lo (one kernel) --------
__global__ void prep_kernel(const float* __restrict__ t1,
                            const float* __restrict__ t2,
                            const float* __restrict__ t3) {
    int i = blockIdx.x * blockDim.x + threadIdx.x;
    if (i < 2 * NMAX) g_count[i] = 0;
    if (i < 3 * 64 * 96) {
        int tt = i / 6144;
        int rem = i % 6144;
        int nn = rem / 96;
        int k2 = rem % 96;
        const float* T = (tt == 0) ? t1 : (tt == 1) ? t2 : t3;
        float x0 = T[(size_t)(2 * k2) * 64 + nn];
        float x1 = T[(size_t)(2 * k2 + 1) * 64 + nn];
        __nv_bfloat162 hh = __floats2bfloat162_rn(x0, x1);
        float r0 = x0 - __low2float(hh);
        float r1 = x1 - __high2float(hh);
        __nv_bfloat162 ll = __floats2bfloat162_rn(r0, r1);
        g_Bh32[i] = *(uint32_t*)&hh;
        g_Bl32[i] = *(uint32_t*)&ll;
    }
}

// ---- CSR build ------------------------------------------------------------
__global__ void hist_kernel(const int* __restrict__ e0, const int* __restrict__ e1, int nE) {
    int i = blockIdx.x * blockDim.x + threadIdx.x;
    if (i >= 2 * nE) return;
    int l = (i < nE) ? 0 : 1;
    const int* p = l ? e1 : e0;
    int e = l ? (i - nE) : i;
    int d = p[e];
    atomicAdd(&g_count[l * NMAX + d], 1);
}

__global__ void scan_partial_kernel(int n) {
    __shared__ int warp_sums[16];
    int l = blockIdx.y;
    int i = blockIdx.x * 512 + threadIdx.x;
    int lane = threadIdx.x & 31;
    int w = threadIdx.x >> 5;
    int v = (i < n) ? g_count[l * NMAX + i] : 0;
    int s = v;
#pragma unroll
    for (int o = 1; o < 32; o <<= 1) {
        int t = __shfl_up_sync(0xFFFFFFFFu, s, o);
        if (lane >= o) s += t;
    }
    if (lane == 31) warp_sums[w] = s;
    __syncthreads();
    if (w == 0) {
        int ws = (lane < 16) ? warp_sums[lane] : 0;
#pragma unroll
        for (int o = 1; o < 16; o <<= 1) {
            int t = __shfl_up_sync(0xFFFFFFFFu, ws, o);
            if (lane >= o) ws += t;
        }
        if (lane < 16) warp_sums[lane] = ws;
    }
    __syncthreads();
    int base = (w > 0) ? warp_sums[w - 1] : 0;
    if (i < n) g_rowstart[l * (NMAX + 1) + i] = base + s - v;
    if (threadIdx.x == 511) g_blocksum[l * 128 + blockIdx.x] = base + s;
}

__global__ void add_offsets_kernel(int n, int nb) {
    int l = blockIdx.y;
    int i = blockIdx.x * blockDim.x + threadIdx.x;
    __shared__ int sP;
    if (threadIdx.x < 32) {
        int myblk = blockIdx.x >> 1;
        int s = 0;
        for (int b = threadIdx.x; b < myblk; b += 32) s += g_blocksum[l * 128 + b];
#pragma unroll
        for (int o = 16; o; o >>= 1) s += __shfl_xor_sync(0xFFFFFFFFu, s, o);
        if (threadIdx.x == 0) sP = s;
    }
    if (blockIdx.x == 0 && threadIdx.x >= 32 && threadIdx.x < 64) {
        int lane = threadIdx.x - 32;
        int s = 0;
        for (int b = lane; b < nb; b += 32) s += g_blocksum[l * 128 + b];
#pragma unroll
        for (int o = 16; o; o >>= 1) s += __shfl_xor_sync(0xFFFFFFFFu, s, o);
        if (lane == 0) g_rowstart[l * (NMAX + 1) + n] = s;
    }
    __syncthreads();
    if (i < n) {
        g_rowstart[l * (NMAX + 1) + i] += sP;
        g_cursor[l * NMAX + i] = 0;
    }
}

__global__ void fill_kernel(const int* __restrict__ e0, const int* __restrict__ e1, int nE) {
    int i = blockIdx.x * blockDim.x + threadIdx.x;
    if (i >= 2 * nE) return;
    int l = (i < nE) ? 0 : 1;
    const int* p = l ? e1 : e0;
    int e = l ? (i - nE) : i;
    int d = p[e];
    int c = p[nE + e];
    int pos = g_rowstart[l * (NMAX + 1) + d] + atomicAdd(&g_cursor[l * NMAX + d], 1);
    g_cols[l * EMAX + pos] = c;
}

// ---- mma.sync GEMM (exact R13 body; Y stores are fp16) --------------------
// Per CTA: rows [rowBase, rowBase+128), all 192 output cols (3 thetas).
// 512 threads / 16 warps: warp (w&7) -> m16 row group, (w>>3) -> n half (32).
// smem: Ah[128][200] | Al[128][200] | Bbuf0{h,l} | Bbuf1{h,l}  (bf16, str 200)
#define A_STRIDE 200
#define OFF_AH 0
#define OFF_AL 51200
#define OFF_B0 102400
#define OFF_B1 153600
#define B_HL   25600      // lo half offset within a B buffer
#define GEMM_SMEM_BYTES 204800

#define MMA(C, A0, A1, A2, A3, B0, B1)                                  \
    asm("mma.sync.aligned.m16n8k16.row.col.f32.bf16.bf16.f32 "          \
        "{%0,%1,%2,%3}, {%4,%5,%6,%7}, {%8,%9}, {%0,%1,%2,%3};"         \
        : "+f"(C.x), "+f"(C.y), "+f"(C.z), "+f"(C.w)                    \
        : "r"(A0), "r"(A1), "r"(A2), "r"(A3), "r"(B0), "r"(B1))

#define LDMX4(R0, R1, R2, R3, ADDR)                                     \
    asm volatile("ldmatrix.sync.aligned.m8n8.x4.shared.b16 "            \
                 "{%0,%1,%2,%3}, [%4];"                                 \
                 : "=r"(R0), "=r"(R1), "=r"(R2), "=r"(R3) : "r"(ADDR))

// Fill one B buffer (theta TT) with cp.async: 64 rows x 24 16B-chunks, hi+lo.
#define CP_FILL(TT, DSTBASE) do {                                             \
    const char* srcH = (const char*)(g_Bh32 + (TT) * 6144);                   \
    const char* srcL = (const char*)(g_Bl32 + (TT) * 6144);                   \
    uint32_t dstH = (DSTBASE);                                                \
    uint32_t dstL = dstH + B_HL;                                              \
    for (int f = tid; f < 1536; f += 512) {                                   \
        int r = f / 24, ck = f % 24;                                          \
        uint32_t doff = (uint32_t)(r * 400 + ck * 16);                        \
        size_t soff = (size_t)r * 384 + (size_t)ck * 16;                      \
        asm volatile("cp.async.cg.shared.global [%0], [%1], 16;"              \
            :: "r"(dstH + doff), "l"(srcH + soff));                           \
        asm volatile("cp.async.cg.shared.global [%0], [%1], 16;"              \
            :: "r"(dstL + doff), "l"(srcL + soff));                           \
    }                                                                         \
    asm volatile("cp.async.commit_group;" ::: "memory");                      \
} while (0)

__global__ __launch_bounds__(512, 1)
void gemm_kernel(const float* __restrict__ A,
                 float* __restrict__ dst,   // n x 192 (theta0 -> cols 0:64)
                 __half* __restrict__ Y,    // n x 128 fp16 (theta1|theta2)
                 int n)
{
    extern __shared__ char smem[];
    uint32_t* Ah32 = (uint32_t*)(smem + OFF_AH);
    uint32_t* Al32 = (uint32_t*)(smem + OFF_AL);

    const int tid = threadIdx.x;
    const int w = tid >> 5;
    const int lane = tid & 31;
    const int mw = w & 7;          // m16 row-group index
    const int nh = w >> 3;         // n half (0: cols 0-31, 1: cols 32-63)
    const int q = lane & 3;
    const int rowBase = blockIdx.x * 128;
    const uint32_t sb = smem_to_u32(smem);

    // ---- Prefetch theta0 B into buffer 0 (overlaps A conversion) ----
    CP_FILL(0, sb + OFF_B0);

    // ---- Convert A rows to bf16 hi/lo in smem (coalesced, conflict-free) --
    for (int f = tid; f < 128 * 96; f += 512) {
        int r = f / 96, k2 = f % 96;
        int gr = rowBase + r;
        float2 v = make_float2(0.f, 0.f);
        if (gr < n) v = *(const float2*)(A + (size_t)gr * DIM + 2 * k2);
        __nv_bfloat162 hh = __floats2bfloat162_rn(v.x, v.y);
        float r0 = v.x - __low2float(hh);
        float r1 = v.y - __high2float(hh);
        __nv_bfloat162 ll = __floats2bfloat162_rn(r0, r1);
        Ah32[r * 100 + k2] = *(uint32_t*)&hh;
        Al32[r * 100 + k2] = *(uint32_t*)&ll;
    }

    // ---- per-lane ldmatrix base addresses ----
    const int raA = (lane & 7) + ((lane >> 3) & 1) * 8;
    const int kaA = ((lane >> 4) & 1) * 8;
    uint32_t aAh = sb + OFF_AH + (uint32_t)((mw * 16 + raA) * A_STRIDE + kaA) * 2;
    uint32_t aAl = aAh + (OFF_AL - OFF_AH);
    const int rbB = (lane & 7) + ((lane >> 4) & 1) * 8;
    const int kbB = ((lane >> 3) & 1) * 8;
    const uint32_t bOffH = (uint32_t)((nh * 32 + rbB) * A_STRIDE + kbB) * 2;

    const int row0 = rowBase + mw * 16 + (lane >> 2);
    const int row1 = row0 + 8;

    asm volatile("cp.async.wait_group 0;" ::: "memory");
    __syncthreads();   // A + theta0 B visible

#pragma unroll
    for (int tt = 0; tt < 3; ++tt) {
        if (tt == 0) {
            CP_FILL(1, sb + OFF_B1);                 // theta1 overlaps theta0
        } else if (tt == 1) {
            CP_FILL(2, sb + OFF_B0);                 // theta2 overlaps theta1
            asm volatile("cp.async.wait_group 1;" ::: "memory");
            __syncthreads();                          // theta1 visible
        } else {
            asm volatile("cp.async.wait_group 0;" ::: "memory");
            __syncthreads();                          // theta2 visible
        }

        const uint32_t bbase = sb + ((tt & 1) ? OFF_B1 : OFF_B0);
        uint32_t aB0h = bbase + bOffH;
        uint32_t aB1h = aB0h + 16 * A_STRIDE * 2;
        uint32_t aB0l = aB0h + B_HL;
        uint32_t aB1l = aB1h + B_HL;

        float4 c0 = make_float4(0.f, 0.f, 0.f, 0.f), c1 = c0, c2 = c0, c3 = c0;

#pragma unroll 2
        for (int ks = 0; ks < 12; ++ks) {
            const uint32_t ko = (uint32_t)ks * 32;   // 16 bf16 = 32 bytes
            uint32_t ah0, ah1, ah2, ah3, al0, al1, al2, al3;
            LDMX4(ah0, ah1, ah2, ah3, aAh + ko);
            LDMX4(al0, al1, al2, al3, aAl + ko);
            uint32_t b0h0, b0h1, b1h0, b1h1;
            LDMX4(b0h0, b0h1, b1h0, b1h1, aB0h + ko);
            uint32_t b2h0, b2h1, b3h0, b3h1;
            LDMX4(b2h0, b2h1, b3h0, b3h1, aB1h + ko);
            uint32_t b0l0, b0l1, b1l0, b1l1;
            LDMX4(b0l0, b0l1, b1l0, b1l1, aB0l + ko);
            uint32_t b2l0, b2l1, b3l0, b3l1;
            LDMX4(b2l0, b2l1, b3l0, b3l1, aB1l + ko);

            MMA(c0, ah0, ah1, ah2, ah3, b0h0, b0h1);
            MMA(c1, ah0, ah1, ah2, ah3, b1h0, b1h1);
            MMA(c2, ah0, ah1, ah2, ah3, b2h0, b2h1);
            MMA(c3, ah0, ah1, ah2, ah3, b3h0, b3h1);
            MMA(c0, ah0, ah1, ah2, ah3, b0l0, b0l1);
            MMA(c1, ah0, ah1, ah2, ah3, b1l0, b1l1);
            MMA(c2, ah0, ah1, ah2, ah3, b2l0, b2l1);
            MMA(c3, ah0, ah1, ah2, ah3, b3l0, b3l1);
            MMA(c0, al0, al1, al2, al3, b0h0, b0h1);
            MMA(c1, al0, al1, al2, al3, b1h0, b1h1);
            MMA(c2, al0, al1, al2, al3, b2h0, b2h1);
            MMA(c3, al0, al1, al2, al3, b3h0, b3h1);
        }

        // ---- Epilogue for this theta ----
        if (tt == 0) {
            // theta0 -> dst cols 0:64, fp32
            const int cb = nh * 32;
#define ST_F32(C, J)                                                          \
            {                                                                 \
                int col = cb + (J) * 8 + 2 * q;                               \
                if (row0 < n)                                                 \
                    *(float2*)(dst + (size_t)row0 * DIM + col) =              \
                        make_float2(C.x, C.y);                                \
                if (row1 < n)                                                 \
                    *(float2*)(dst + (size_t)row1 * DIM + col) =              \
                        make_float2(C.z, C.w);                                \
            }
            ST_F32(c0, 0) ST_F32(c1, 1) ST_F32(c2, 2) ST_F32(c3, 3)
#undef ST_F32
        } else {
            // theta1/theta2 -> Y (fp16), row stride 128 halves
            const int cb = ((tt == 2) ? 64 : 0) + nh * 32;
#define ST_F16(C, J)                                                          \
            {                                                                 \
                int col = cb + (J) * 8 + 2 * q;                               \
                if (row0 < n)                                                 \
                    *(__half2*)(Y + (size_t)row0 * 128 + col) =               \
                        __floats2half2_rn(C.x, C.y);                          \
                if (row1 < n)                                                 \
                    *(__half2*)(Y + (size_t)row1 * 128 + col) =               \
                        __floats2half2_rn(C.z, C.w);                          \
            }
            ST_F16(c0, 0) ST_F16(c1, 1) ST_F16(c2, 2) ST_F16(c3, 3)
#undef ST_F16
        }

        if (tt == 0) __syncthreads();   // buffer0 readers done before theta2 fill lands
    }
}

// ---- Aggregation: warp per (node, list), fp16 gather, fp32 accumulate -----
__global__ void agg_kernel(const __half* __restrict__ Y, float* __restrict__ dst, int n)
{
    int gw = (blockIdx.x * blockDim.x + threadIdx.x) >> 5;
    int lane = threadIdx.x & 31;
    int l = blockIdx.y;
    if (gw >= n) return;
    const int* rs = g_rowstart + l * (NMAX + 1);
    const int* cs = g_cols + l * EMAX;
    int s = __ldg(rs + gw);
    int e = __ldg(rs + gw + 1);
    // Each lane owns 2 consecutive cols: half2 at index l*32 + lane in a
    // 64-half2 row.
    const __half2* Yb = (const __half2*)Y + l * 32 + lane;
    float ax = 0.f, ay = 0.f;
    int j = s;
    for (; j + 4 <= e; j += 4) {
        int c0 = cs[j], c1 = cs[j + 1], c2 = cs[j + 2], c3 = cs[j + 3];
        float2 v0 = __half22float2(Yb[(size_t)c0 * 64]);
        float2 v1 = __half22float2(Yb[(size_t)c1 * 64]);
        float2 v2 = __half22float2(Yb[(size_t)c2 * 64]);
        float2 v3 = __half22float2(Yb[(size_t)c3 * 64]);
        ax += (v0.x + v1.x) + (v2.x + v3.x);
        ay += (v0.y + v1.y) + (v2.y + v3.y);
    }
    for (; j < e; ++j) {
        float2 v = __half22float2(Yb[(size_t)cs[j] * 64]);
        ax += v.x; ay += v.y;
    }
    *(float2*)(dst + (size_t)gw * DIM + 64 + l * 64 + lane * 2) =
        make_float2(ax, ay);
}

// ---------------------------------------------------------------------------
extern "C" void kernel_launch(void* const* d_in, const int* in_sizes, int n_in,
                              void* d_out, int out_size)
{
    const float* emb = (const float*)d_in[0];
    const float* t1  = (const float*)d_in[1];
    const float* t2  = (const float*)d_in[2];
    const float* t3  = (const float*)d_in[3];
    const int*   e0  = (const int*)d_in[4];
    const int*   e1  = (const int*)d_in[5];

    int n  = in_sizes[0] / DIM;
    int nE = in_sizes[4] / 2;
    float* out = (float*)d_out;

    void *p_emb1_v, *p_Y_v;
    cudaGetSymbolAddress(&p_emb1_v, g_emb1);
    cudaGetSymbolAddress(&p_Y_v, g_Yh);
    float*  p_emb1 = (float*)p_emb1_v;
    __half* p_Y    = (__half*)p_Y_v;

    cudaFuncSetAttribute(gemm_kernel, cudaFuncAttributeMaxDynamicSharedMemorySize,
                         GEMM_SMEM_BYTES);

    int nb = (n + 511) / 512;
    int gemm_blocks = (n + 127) / 128;
    dim3 agg_grid((n * 32 + 255) / 256, 2);

    // gemm1 at launch slot #4 (the slot ncu captures) for profiling.
    prep_kernel<<<(2 * NMAX + 255) / 256, 256>>>(t1, t2, t3);              // 1
    hist_kernel<<<(2 * nE + 255) / 256, 256>>>(e0, e1, nE);                // 2
    dim3 gscan(nb, 2);
    scan_partial_kernel<<<gscan, 512>>>(n);                                // 3
    gemm_kernel<<<gemm_blocks, 512, GEMM_SMEM_BYTES>>>(emb, p_emb1, p_Y, n); // 4
    dim3 goff((n + 255) / 256, 2);
    add_offsets_kernel<<<goff, 256>>>(n, nb);                              // 5
    fill_kernel<<<(2 * nE + 255) / 256, 256>>>(e0, e1, nE);                // 6
    agg_kernel<<<agg_grid, 256>>>(p_Y, p_emb1, n);                         // 7
    gemm_kernel<<<gemm_blocks, 512, GEMM_SMEM_BYTES>>>(p_emb1, out, p_Y, n); // 8
    agg_kernel<<<agg_grid, 256>>>(p_Y, out, n);                            // 9
}

// round 16
// speedup vs baseline: 1.0629x; 1.0627x over previous
#include <cuda_runtime.h>
#include <cuda_bf16.h>
#include <cstdint>

// ---------------------------------------------------------------------------
// IterativeEmbeddingModel: 2 iterations of
//   emb <- concat(emb@T1, seg_sum(emb[col],row)@T2, seg_sum_anti(...)@T3)
// R16 (on R13 champion, 184.3us):
//  - Y reverted to fp32 (R15 fp16 was perf-neutral: agg is NOT byte-bound;
//    restores rel_err 6.4e-6 headroom).
//  - CSR chain (hist/scan/offsets/fill) forked onto a cudaStreamNonBlocking
//    stream, overlapped with gemm1. R2's fork failed because
//    cudaStreamPerThread is a BLOCKING stream: legacy-stream implicit sync
//    serialized the branches (612.38 vs 612.35 proved zero overlap).
//    Non-blocking streams are exempt from legacy implicit sync.
//  - GEMM/agg bodies = exact R13.
// ---------------------------------------------------------------------------

#define NMAX 50000
#define EMAX 400000
#define DIM  192
#define PP   64

// Scratch (device globals; no allocation APIs allowed)
__device__ int      g_count[2 * NMAX];
__device__ int      g_cursor[2 * NMAX];
__device__ int      g_rowstart[2 * (NMAX + 1)];
__device__ int      g_blocksum[2 * 128];
__device__ int      g_cols[2 * EMAX];
__device__ float    g_emb1[(size_t)NMAX * DIM];   // iteration-1 output
__device__ float    g_Y[(size_t)NMAX * 128];      // [Y2 | Y3] per row
__device__ uint32_t g_Bh32[3 * 64 * 96];          // thetas bf16-hi, [t][n][k2]
__device__ uint32_t g_Bl32[3 * 64 * 96];          // thetas bf16-lo

__device__ __forceinline__ uint32_t smem_to_u32(const void* p) {
    uint32_t a;
    asm("{ .reg .u64 t; cvta.to.shared.u64 t, %1; cvt.u32.u64 %0, t; }"
        : "=r"(a) : "l"(p));
    return a;
}

// ---- prep: zero counts + convert thetas to bf16 hi/lo (one kernel) --------
__global__ void prep_kernel(const float* __restrict__ t1,
                            const float* __restrict__ t2,
                            const float* __restrict__ t3) {
    int i = blockIdx.x * blockDim.x + threadIdx.x;
    if (i < 2 * NMAX) g_count[i] = 0;
    if (i < 3 * 64 * 96) {
        int tt = i / 6144;
        int rem = i % 6144;
        int nn = rem / 96;
        int k2 = rem % 96;
        const float* T = (tt == 0) ? t1 : (tt == 1) ? t2 : t3;
        float x0 = T[(size_t)(2 * k2) * 64 + nn];
        float x1 = T[(size_t)(2 * k2 + 1) * 64 + nn];
        __nv_bfloat162 hh = __floats2bfloat162_rn(x0, x1);
        float r0 = x0 - __low2float(hh);
        float r1 = x1 - __high2float(hh);
        __nv_bfloat162 ll = __floats2bfloat162_rn(r0, r1);
        g_Bh32[i] = *(uint32_t*)&hh;
        g_Bl32[i] = *(uint32_t*)&ll;
    }
}

// ---- CSR build ------------------------------------------------------------
__global__ void hist_kernel(const int* __restrict__ e0, const int* __restrict__ e1, int nE) {
    int i = blockIdx.x * blockDim.x + threadIdx.x;
    if (i >= 2 * nE) return;
    int l = (i < nE) ? 0 : 1;
    const int* p = l ? e1 : e0;
    int e = l ? (i - nE) : i;
    int d = p[e];
    atomicAdd(&g_count[l * NMAX + d], 1);
}

__global__ void scan_partial_kernel(int n) {
    __shared__ int warp_sums[16];
    int l = blockIdx.y;
    int i = blockIdx.x * 512 + threadIdx.x;
    int lane = threadIdx.x & 31;
    int w = threadIdx.x >> 5;
    int v = (i < n) ? g_count[l * NMAX + i] : 0;
    int s = v;
#pragma unroll
    for (int o = 1; o < 32; o <<= 1) {
        int t = __shfl_up_sync(0xFFFFFFFFu, s, o);
        if (lane >= o) s += t;
    }
    if (lane == 31) warp_sums[w] = s;
    __syncthreads();
    if (w == 0) {
        int ws = (lane < 16) ? warp_sums[lane] : 0;
#pragma unroll
        for (int o = 1; o < 16; o <<= 1) {
            int t = __shfl_up_sync(0xFFFFFFFFu, ws, o);
            if (lane >= o) ws += t;
        }
        if (lane < 16) warp_sums[lane] = ws;
    }
    __syncthreads();
    int base = (w > 0) ? warp_sums[w - 1] : 0;
    if (i < n) g_rowstart[l * (NMAX + 1) + i] = base + s - v;
    if (threadIdx.x == 511) g_blocksum[l * 128 + blockIdx.x] = base + s;
}

__global__ void add_offsets_kernel(int n, int nb) {
    int l = blockIdx.y;
    int i = blockIdx.x * blockDim.x + threadIdx.x;
    __shared__ int sP;
    if (threadIdx.x < 32) {
        int myblk = blockIdx.x >> 1;
        int s = 0;
        for (int b = threadIdx.x; b < myblk; b += 32) s += g_blocksum[l * 128 + b];
#pragma unroll
        for (int o = 16; o; o >>= 1) s += __shfl_xor_sync(0xFFFFFFFFu, s, o);
        if (threadIdx.x == 0) sP = s;
    }
    if (blockIdx.x == 0 && threadIdx.x >= 32 && threadIdx.x < 64) {
        int lane = threadIdx.x - 32;
        int s = 0;
        for (int b = lane; b < nb; b += 32) s += g_blocksum[l * 128 + b];
#pragma unroll
        for (int o = 16; o; o >>= 1) s += __shfl_xor_sync(0xFFFFFFFFu, s, o);
        if (lane == 0) g_rowstart[l * (NMAX + 1) + n] = s;
    }
    __syncthreads();
    if (i < n) {
        g_rowstart[l * (NMAX + 1) + i] += sP;
        g_cursor[l * NMAX + i] = 0;
    }
}

__global__ void fill_kernel(const int* __restrict__ e0, const int* __restrict__ e1, int nE) {
    int i = blockIdx.x * blockDim.x + threadIdx.x;
    if (i >= 2 * nE) return;
    int l = (i < nE) ? 0 : 1;
    const int* p = l ? e1 : e0;
    int e = l ? (i - nE) : i;
    int d = p[e];
    int c = p[nE + e];
    int pos = g_rowstart[l * (NMAX + 1) + d] + atomicAdd(&g_cursor[l * NMAX + d], 1);
    g_cols[l * EMAX + pos] = c;
}

// ---- mma.sync GEMM (exact R13 body) ---------------------------------------
// Per CTA: rows [rowBase, rowBase+128), all 192 output cols (3 thetas).
// 512 threads / 16 warps: warp (w&7) -> m16 row group, (w>>3) -> n half (32).
// smem: Ah[128][200] | Al[128][200] | Bbuf0{h,l} | Bbuf1{h,l}  (bf16, str 200)
#define A_STRIDE 200
#define OFF_AH 0
#define OFF_AL 51200
#define OFF_B0 102400
#define OFF_B1 153600
#define B_HL   25600      // lo half offset within a B buffer
#define GEMM_SMEM_BYTES 204800

#define MMA(C, A0, A1, A2, A3, B0, B1)                                  \
    asm("mma.sync.aligned.m16n8k16.row.col.f32.bf16.bf16.f32 "          \
        "{%0,%1,%2,%3}, {%4,%5,%6,%7}, {%8,%9}, {%0,%1,%2,%3};"         \
        : "+f"(C.x), "+f"(C.y), "+f"(C.z), "+f"(C.w)                    \
        : "r"(A0), "r"(A1), "r"(A2), "r"(A3), "r"(B0), "r"(B1))

#define LDMX4(R0, R1, R2, R3, ADDR)                                     \
    asm volatile("ldmatrix.sync.aligned.m8n8.x4.shared.b16 "            \
                 "{%0,%1,%2,%3}, [%4];"                                 \
                 : "=r"(R0), "=r"(R1), "=r"(R2), "=r"(R3) : "r"(ADDR))

// Fill one B buffer (theta TT) with cp.async: 64 rows x 24 16B-chunks, hi+lo.
#define CP_FILL(TT, DSTBASE) do {                                             \
    const char* srcH = (const char*)(g_Bh32 + (TT) * 6144);                   \
    const char* srcL = (const char*)(g_Bl32 + (TT) * 6144);                   \
    uint32_t dstH = (DSTBASE);                                                \
    uint32_t dstL = dstH + B_HL;                                              \
    for (int f = tid; f < 1536; f += 512) {                                   \
        int r = f / 24, ck = f % 24;                                          \
        uint32_t doff = (uint32_t)(r * 400 + ck * 16);                        \
        size_t soff = (size_t)r * 384 + (size_t)ck * 16;                      \
        asm volatile("cp.async.cg.shared.global [%0], [%1], 16;"              \
            :: "r"(dstH + doff), "l"(srcH + soff));                           \
        asm volatile("cp.async.cg.shared.global [%0], [%1], 16;"              \
            :: "r"(dstL + doff), "l"(srcL + soff));                           \
    }                                                                         \
    asm volatile("cp.async.commit_group;" ::: "memory");                      \
} while (0)

__global__ __launch_bounds__(512, 1)
void gemm_kernel(const float* __restrict__ A,
                 float* __restrict__ dst,   // n x 192 (theta0 -> cols 0:64)
                 float* __restrict__ Y,     // n x 128 (theta1|theta2)
                 int n)
{
    extern __shared__ char smem[];
    uint32_t* Ah32 = (uint32_t*)(smem + OFF_AH);
    uint32_t* Al32 = (uint32_t*)(smem + OFF_AL);

    const int tid = threadIdx.x;
    const int w = tid >> 5;
    const int lane = tid & 31;
    const int mw = w & 7;          // m16 row-group index
    const int nh = w >> 3;         // n half (0: cols 0-31, 1: cols 32-63)
    const int q = lane & 3;
    const int rowBase = blockIdx.x * 128;
    const uint32_t sb = smem_to_u32(smem);

    // ---- Prefetch theta0 B into buffer 0 (overlaps A conversion) ----
    CP_FILL(0, sb + OFF_B0);

    // ---- Convert A rows to bf16 hi/lo in smem (coalesced, conflict-free) --
    for (int f = tid; f < 128 * 96; f += 512) {
        int r = f / 96, k2 = f % 96;
        int gr = rowBase + r;
        float2 v = make_float2(0.f, 0.f);
        if (gr < n) v = *(const float2*)(A + (size_t)gr * DIM + 2 * k2);
        __nv_bfloat162 hh = __floats2bfloat162_rn(v.x, v.y);
        float r0 = v.x - __low2float(hh);
        float r1 = v.y - __high2float(hh);
        __nv_bfloat162 ll = __floats2bfloat162_rn(r0, r1);
        Ah32[r * 100 + k2] = *(uint32_t*)&hh;
        Al32[r * 100 + k2] = *(uint32_t*)&ll;
    }

    // ---- per-lane ldmatrix base addresses ----
    const int raA = (lane & 7) + ((lane >> 3) & 1) * 8;
    const int kaA = ((lane >> 4) & 1) * 8;
    uint32_t aAh = sb + OFF_AH + (uint32_t)((mw * 16 + raA) * A_STRIDE + kaA) * 2;
    uint32_t aAl = aAh + (OFF_AL - OFF_AH);
    const int rbB = (lane & 7) + ((lane >> 4) & 1) * 8;
    const int kbB = ((lane >> 3) & 1) * 8;
    const uint32_t bOffH = (uint32_t)((nh * 32 + rbB) * A_STRIDE + kbB) * 2;

    const int row0 = rowBase + mw * 16 + (lane >> 2);
    const int row1 = row0 + 8;

    asm volatile("cp.async.wait_group 0;" ::: "memory");
    __syncthreads();   // A + theta0 B visible

#pragma unroll
    for (int tt = 0; tt < 3; ++tt) {
        if (tt == 0) {
            CP_FILL(1, sb + OFF_B1);                 // theta1 overlaps theta0
        } else if (tt == 1) {
            CP_FILL(2, sb + OFF_B0);                 // theta2 overlaps theta1
            asm volatile("cp.async.wait_group 1;" ::: "memory");
            __syncthreads();                          // theta1 visible
        } else {
            asm volatile("cp.async.wait_group 0;" ::: "memory");
            __syncthreads();                          // theta2 visible
        }

        const uint32_t bbase = sb + ((tt & 1) ? OFF_B1 : OFF_B0);
        uint32_t aB0h = bbase + bOffH;
        uint32_t aB1h = aB0h + 16 * A_STRIDE * 2;
        uint32_t aB0l = aB0h + B_HL;
        uint32_t aB1l = aB1h + B_HL;

        float4 c0 = make_float4(0.f, 0.f, 0.f, 0.f), c1 = c0, c2 = c0, c3 = c0;

#pragma unroll 2
        for (int ks = 0; ks < 12; ++ks) {
            const uint32_t ko = (uint32_t)ks * 32;   // 16 bf16 = 32 bytes
            uint32_t ah0, ah1, ah2, ah3, al0, al1, al2, al3;
            LDMX4(ah0, ah1, ah2, ah3, aAh + ko);
            LDMX4(al0, al1, al2, al3, aAl + ko);
            uint32_t b0h0, b0h1, b1h0, b1h1;
            LDMX4(b0h0, b0h1, b1h0, b1h1, aB0h + ko);
            uint32_t b2h0, b2h1, b3h0, b3h1;
            LDMX4(b2h0, b2h1, b3h0, b3h1, aB1h + ko);
            uint32_t b0l0, b0l1, b1l0, b1l1;
            LDMX4(b0l0, b0l1, b1l0, b1l1, aB0l + ko);
            uint32_t b2l0, b2l1, b3l0, b3l1;
            LDMX4(b2l0, b2l1, b3l0, b3l1, aB1l + ko);

            MMA(c0, ah0, ah1, ah2, ah3, b0h0, b0h1);
            MMA(c1, ah0, ah1, ah2, ah3, b1h0, b1h1);
            MMA(c2, ah0, ah1, ah2, ah3, b2h0, b2h1);
            MMA(c3, ah0, ah1, ah2, ah3, b3h0, b3h1);
            MMA(c0, ah0, ah1, ah2, ah3, b0l0, b0l1);
            MMA(c1, ah0, ah1, ah2, ah3, b1l0, b1l1);
            MMA(c2, ah0, ah1, ah2, ah3, b2l0, b2l1);
            MMA(c3, ah0, ah1, ah2, ah3, b3l0, b3l1);
            MMA(c0, al0, al1, al2, al3, b0h0, b0h1);
            MMA(c1, al0, al1, al2, al3, b1h0, b1h1);
            MMA(c2, al0, al1, al2, al3, b2h0, b2h1);
            MMA(c3, al0, al1, al2, al3, b3h0, b3h1);
        }

        // ---- Epilogue for this theta ----
        float* outp = (tt == 0) ? dst : Y;
        const int ostr = (tt == 0) ? DIM : 128;
        const int cb = ((tt == 2) ? 64 : 0) + nh * 32;
#define ST_TILE(C, J)                                                         \
        {                                                                     \
            int col = cb + (J) * 8 + 2 * q;                                   \
            if (row0 < n)                                                     \
                *(float2*)(outp + (size_t)row0 * ostr + col) =                \
                    make_float2(C.x, C.y);                                    \
            if (row1 < n)                                                     \
                *(float2*)(outp + (size_t)row1 * ostr + col) =                \
                    make_float2(C.z, C.w);                                    \
        }
        ST_TILE(c0, 0) ST_TILE(c1, 1) ST_TILE(c2, 2) ST_TILE(c3, 3)
#undef ST_TILE

        if (tt == 0) __syncthreads();   // buffer0 readers done before theta2 fill lands
    }
}

// ---- Aggregation: warp per (node, list), atomic-free CSR gather -----------
__global__ void agg_kernel(const float* __restrict__ Y, float* __restrict__ dst, int n)
{
    int gw = (blockIdx.x * blockDim.x + threadIdx.x) >> 5;
    int lane = threadIdx.x & 31;
    int l = blockIdx.y;
    if (gw >= n) return;
    const int* rs = g_rowstart + l * (NMAX + 1);
    const int* cs = g_cols + l * EMAX;
    int s = __ldg(rs + gw);
    int e = __ldg(rs + gw + 1);
    const float* Yb = Y + l * 64 + lane * 2;
    float ax = 0.f, ay = 0.f;
    int j = s;
    for (; j + 4 <= e; j += 4) {
        int c0 = cs[j], c1 = cs[j + 1], c2 = cs[j + 2], c3 = cs[j + 3];
        float2 v0 = *(const float2*)(Yb + (size_t)c0 * 128);
        float2 v1 = *(const float2*)(Yb + (size_t)c1 * 128);
        float2 v2 = *(const float2*)(Yb + (size_t)c2 * 128);
        float2 v3 = *(const float2*)(Yb + (size_t)c3 * 128);
        ax += (v0.x + v1.x) + (v2.x + v3.x);
        ay += (v0.y + v1.y) + (v2.y + v3.y);
    }
    for (; j < e; ++j) {
        float2 v = *(const float2*)(Yb + (size_t)cs[j] * 128);
        ax += v.x; ay += v.y;
    }
    *(float2*)(dst + (size_t)gw * DIM + 64 + l * 64 + lane * 2) =
        make_float2(ax, ay);
}

// ---------------------------------------------------------------------------
extern "C" void kernel_launch(void* const* d_in, const int* in_sizes, int n_in,
                              void* d_out, int out_size)
{
    const float* emb = (const float*)d_in[0];
    const float* t1  = (const float*)d_in[1];
    const float* t2  = (const float*)d_in[2];
    const float* t3  = (const float*)d_in[3];
    const int*   e0  = (const int*)d_in[4];
    const int*   e1  = (const int*)d_in[5];

    int n  = in_sizes[0] / DIM;
    int nE = in_sizes[4] / 2;
    float* out = (float*)d_out;

    void *p_emb1_v, *p_Y_v;
    cudaGetSymbolAddress(&p_emb1_v, g_emb1);
    cudaGetSymbolAddress(&p_Y_v, g_Y);
    float* p_emb1 = (float*)p_emb1_v;
    float* p_Y    = (float*)p_Y_v;

    cudaFuncSetAttribute(gemm_kernel, cudaFuncAttributeMaxDynamicSharedMemorySize,
                         GEMM_SMEM_BYTES);

    // Lazily-created NON-BLOCKING side stream + fork/join events.
    // Non-blocking => exempt from legacy-stream implicit synchronization
    // (cudaStreamPerThread is blocking, which is why R2's fork serialized).
    // Created once on first (eager/correctness) call, reused during capture.
    static cudaStream_t side = nullptr;
    static cudaEvent_t evFork = nullptr, evJoin = nullptr;
    if (!side) {
        cudaStreamCreateWithFlags(&side, cudaStreamNonBlocking);
        cudaEventCreateWithFlags(&evFork, cudaEventDisableTiming);
        cudaEventCreateWithFlags(&evJoin, cudaEventDisableTiming);
    }

    int nb = (n + 511) / 512;
    int gemm_blocks = (n + 127) / 128;
    dim3 agg_grid((n * 32 + 255) / 256, 2);
    dim3 gscan(nb, 2);
    dim3 goff((n + 255) / 256, 2);

    // prep: needed by BOTH branches (zeroed counts for hist, bf16 thetas for gemm)
    prep_kernel<<<(2 * NMAX + 255) / 256, 256>>>(t1, t2, t3);

    // Fork: CSR chain on side stream, concurrent with gemm1 on legacy.
    cudaEventRecord(evFork, 0);
    cudaStreamWaitEvent(side, evFork, 0);
    hist_kernel<<<(2 * nE + 255) / 256, 256, 0, side>>>(e0, e1, nE);
    scan_partial_kernel<<<gscan, 512, 0, side>>>(n);
    add_offsets_kernel<<<goff, 256, 0, side>>>(n, nb);
    fill_kernel<<<(2 * nE + 255) / 256, 256, 0, side>>>(e0, e1, nE);
    cudaEventRecord(evJoin, side);

    // gemm1 (legacy stream; ncu capture slot)
    gemm_kernel<<<gemm_blocks, 512, GEMM_SMEM_BYTES>>>(emb, p_emb1, p_Y, n);

    // Join: agg1 needs both gemm1 (Y) and the CSR.
    cudaStreamWaitEvent(0, evJoin, 0);
    agg_kernel<<<agg_grid, 256>>>(p_Y, p_emb1, n);

    // iteration 2
    gemm_kernel<<<gemm_blocks, 512, GEMM_SMEM_BYTES>>>(p_emb1, out, p_Y, n);
    agg_kernel<<<agg_grid, 256>>>(p_Y, out, n);
}